// round 1
// baseline (speedup 1.0000x reference)
#include <cuda_runtime.h>
#include <cstdint>

// Problem constants (fixed shapes per reference)
#define N_NODES 8192
#define KNN     32
#define NE      (N_NODES * KNN)
#define WARPS_PER_BLOCK 8
#define FULLMASK 0xffffffffu

// Scratch (no allocation allowed): packed position table + attr table
__device__ float4 g_packed[N_NODES];  // {cx, cy, sq, 0}
__device__ float4 g_attr[N_NODES];    // {w, h, cx, cy}

__global__ void pack_kernel(const float* __restrict__ loc) {
    int i = blockIdx.x * blockDim.x + threadIdx.x;
    if (i >= N_NODES) return;
    const float* r = loc + i * 10;
    float w  = r[4];
    float h  = r[5];
    float cx = r[6];
    float cy = r[7];
    // sq matches jnp.sum(pos*pos, axis=1): rn(cx*cx) + rn(cy*cy), no fma
    float sq = __fadd_rn(__fmul_rn(cx, cx), __fmul_rn(cy, cy));
    g_packed[i] = make_float4(cx, cy, sq, 0.0f);
    g_attr[i]   = make_float4(w, h, cx, cy);
}

// monotonic float->uint mapping (handles tiny negative d2 from rounding)
__device__ __forceinline__ unsigned int fkey(float f) {
    unsigned int u = __float_as_uint(f);
    return (u & 0x80000000u) ? ~u : (u | 0x80000000u);
}

__device__ __forceinline__ unsigned long long warp_max64(unsigned long long v) {
    #pragma unroll
    for (int off = 16; off > 0; off >>= 1) {
        unsigned long long o = __shfl_xor_sync(FULLMASK, v, off);
        if (o > v) v = o;
    }
    return v;
}

__global__ void __launch_bounds__(32 * WARPS_PER_BLOCK)
knn_kernel(float* __restrict__ out) {
    const int warp = threadIdx.x >> 5;
    const int lane = threadIdx.x & 31;
    const int q = blockIdx.x * WARPS_PER_BLOCK + warp;

    const float4 pq = g_packed[q];
    const float qx = pq.x, qy = pq.y, sqi = pq.z;
    const float INF = __int_as_float(0x7f800000);

    // --- key for candidate j, exactly replicating reference fp32 math ---
    auto compute_key = [&](int j) -> unsigned long long {
        float4 p = g_packed[j];
        float dot = __fmaf_rn(p.y, qy, __fmul_rn(p.x, qx)); // Eigen-style fma chain
        float d2  = __fsub_rn(__fadd_rn(sqi, p.z), __fmul_rn(2.0f, dot));
        if (j == q) d2 = INF;  // diagonal -> +inf (no self loops)
        return ((unsigned long long)fkey(d2) << 32) | (unsigned int)j;
    };

    // init set with chunk 0 (candidates 0..31)
    unsigned long long slot = compute_key(lane);
    unsigned long long curMax = warp_max64(slot);

    // scan remaining candidates
    for (int base = 32; base < N_NODES; base += 32) {
        unsigned long long key = compute_key(base + lane);
        unsigned int mask = __ballot_sync(FULLMASK, key < curMax);
        while (mask) {
            int srcl = __ffs(mask) - 1;
            mask &= mask - 1;
            unsigned long long kk = __shfl_sync(FULLMASK, key, srcl);
            if (kk < curMax) {  // may have shrunk since ballot
                // evict the unique slot holding curMax
                unsigned int mm = __ballot_sync(FULLMASK, slot == curMax);
                int victim = __ffs(mm) - 1;
                if (lane == victim) slot = kk;
                curMax = warp_max64(slot);
            } else {
                __syncwarp(FULLMASK);  // keep warp converged with the ballot above
            }
        }
    }

    // --- bitonic sort ascending: lane l ends with rank-l key ---
    unsigned long long v = slot;
    #pragma unroll
    for (int k2 = 2; k2 <= 32; k2 <<= 1) {
        #pragma unroll
        for (int j = k2 >> 1; j > 0; j >>= 1) {
            unsigned long long o = __shfl_xor_sync(FULLMASK, v, j);
            bool up      = ((lane & k2) == 0);
            bool lower   = ((lane & j) == 0);
            bool keepmin = (up == lower);
            bool take    = keepmin ? (o < v) : (o > v);
            if (take) v = o;
        }
    }

    // --- outputs ---
    const int e = q * KNN + lane;
    const int s = (int)(unsigned int)(v & 0xffffffffu);

    out[e]      = (float)s;  // edge_index[0] (sources)
    out[NE + e] = (float)q;  // edge_index[1] (targets)

    float4 as = g_attr[s];
    float4 at = g_attr[q];
    float hsum = __fadd_rn(as.y, at.y);
    float f1 = __fdiv_rn(__fmul_rn(2.0f, __fsub_rn(as.z, at.z)), hsum);
    float f2 = __fdiv_rn(__fmul_rn(2.0f, __fsub_rn(as.w, at.w)), hsum);
    float f3 = logf(__fdiv_rn(as.x, at.x));
    float f4 = logf(__fdiv_rn(as.y, at.y));

    float4* ao = reinterpret_cast<float4*>(out + 2 * NE) + e;
    *ao = make_float4(f1, f2, f3, f4);
}

extern "C" void kernel_launch(void* const* d_in, const int* in_sizes, int n_in,
                              void* d_out, int out_size) {
    // inputs (metadata order): [0]=x (unused), [1]=location_info, [2]=k (unused, fixed 32)
    const float* loc = (const float*)d_in[1];
    float* out = (float*)d_out;

    pack_kernel<<<(N_NODES + 255) / 256, 256>>>(loc);
    knn_kernel<<<N_NODES / WARPS_PER_BLOCK, 32 * WARPS_PER_BLOCK>>>(out);
}

// round 2
// speedup vs baseline: 1.6598x; 1.6598x over previous
#include <cuda_runtime.h>
#include <cstdint>

#define N_NODES 8192
#define KNN     32
#define NE      (N_NODES * KNN)
#define WPB     8
#define FULL    0xffffffffu

// Scratch (no allocation allowed)
__device__ float4 g_packed[N_NODES];  // {cx, cy, sq, 0}
__device__ float4 g_attr[N_NODES];    // {w, h, cx, cy}

__global__ void pack_kernel(const float* __restrict__ loc) {
    int i = blockIdx.x * blockDim.x + threadIdx.x;
    if (i >= N_NODES) return;
    const float* r = loc + i * 10;
    float w  = r[4];
    float h  = r[5];
    float cx = r[6];
    float cy = r[7];
    // sq matches jnp.sum(pos*pos): rn(cx*cx)+rn(cy*cy), no fma
    float sq = __fadd_rn(__fmul_rn(cx, cx), __fmul_rn(cy, cy));
    g_packed[i] = make_float4(cx, cy, sq, 0.0f);
    g_attr[i]   = make_float4(w, h, cx, cy);
}

// monotonic float<->uint order mapping
__device__ __forceinline__ unsigned fkey(float f) {
    unsigned u = __float_as_uint(f);
    return (u & 0x80000000u) ? ~u : (u | 0x80000000u);
}
__device__ __forceinline__ float unfkey(unsigned k) {
    unsigned u = (k & 0x80000000u) ? (k ^ 0x80000000u) : ~k;
    return __uint_as_float(u);
}

__global__ void __launch_bounds__(32 * WPB)
knn_kernel(float* __restrict__ out) {
    const int lane = threadIdx.x & 31;
    const int q    = blockIdx.x * WPB + (threadIdx.x >> 5);

    const float4 pq  = g_packed[q];
    const float  qx  = pq.x, qy = pq.y, sqi = pq.z;
    const float  m2x = -2.0f * qx, m2y = -2.0f * qy;  // exact (×2)
    const float  INF = __int_as_float(0x7f800000);

    // exact reference-rounded key: (fkey(d2) << 32) | idx
    auto exact_key = [&](float px, float py, float pz, int j) -> unsigned long long {
        float dot = __fmaf_rn(py, qy, __fmul_rn(px, qx));
        float d2  = __fsub_rn(__fadd_rn(sqi, pz), __fmul_rn(2.0f, dot));
        if (j == q) d2 = INF;  // no self loops
        return ((unsigned long long)fkey(d2) << 32) | (unsigned)j;
    };

    // ---- init: exact keys for candidates 0..31, bitonic sort ascending ----
    unsigned long long slot;
    {
        float4 p = g_packed[lane];
        slot = exact_key(p.x, p.y, p.z, lane);
    }
    #pragma unroll
    for (int k2 = 2; k2 <= 32; k2 <<= 1) {
        #pragma unroll
        for (int j = k2 >> 1; j > 0; j >>= 1) {
            unsigned long long o = __shfl_xor_sync(FULL, slot, j);
            bool keepmin = (((lane & k2) == 0) == ((lane & j) == 0));
            bool take    = keepmin ? (o < slot) : (o > slot);
            if (take) slot = o;
        }
    }
    // slots now sorted ascending by lane; lane 31 holds the running max.

    // conservative score-space threshold (slack >> max rounding discrepancy)
    const float SLACK = 2e-5f;
    float thresh;
    {
        unsigned hi = (unsigned)(__shfl_sync(FULL, slot, 31) >> 32);
        thresh = unfkey(hi) - sqi + SLACK;
    }

    const float4* __restrict__ pk = g_packed;

    #pragma unroll 2
    for (int base = 32; base < N_NODES; base += 32) {
        float4 p = pk[base + lane];
        // cheap monotone surrogate: sq_j - 2*px*qx - 2*py*qy (2 FFMA)
        float score = __fmaf_rn(p.y, m2y, __fmaf_rn(p.x, m2x, p.z));
        unsigned mask = __ballot_sync(FULL, score < thresh);
        if (mask) {
            do {
                int srcl = __ffs(mask) - 1;
                mask &= mask - 1;
                float px = __shfl_sync(FULL, p.x, srcl);
                float py = __shfl_sync(FULL, p.y, srcl);
                float pz = __shfl_sync(FULL, p.z, srcl);
                unsigned long long kk = exact_key(px, py, pz, base + srcl);
                // sorted shift-insert; self-rejecting when kk >= slot[31]
                bool gt = (slot > kk);
                unsigned m = __ballot_sync(FULL, gt);
                unsigned long long o = __shfl_up_sync(FULL, slot, 1);
                if (gt) slot = (lane == __ffs(m) - 1) ? kk : o;
            } while (mask);
            unsigned hi = (unsigned)(__shfl_sync(FULL, slot, 31) >> 32);
            thresh = unfkey(hi) - sqi + SLACK;
        }
    }

    // ---- outputs (slots already ascending = top_k order) ----
    const int e = q * KNN + lane;
    const int s = (int)(unsigned)(slot & 0xffffffffu);

    out[e]      = (float)s;  // edge_index[0] (sources)
    out[NE + e] = (float)q;  // edge_index[1] (targets)

    float4 as = g_attr[s];
    float4 at = g_attr[q];
    float hsum = __fadd_rn(as.y, at.y);
    float f1 = __fdiv_rn(__fmul_rn(2.0f, __fsub_rn(as.z, at.z)), hsum);
    float f2 = __fdiv_rn(__fmul_rn(2.0f, __fsub_rn(as.w, at.w)), hsum);
    float f3 = logf(__fdiv_rn(as.x, at.x));
    float f4 = logf(__fdiv_rn(as.y, at.y));

    float4* ao = reinterpret_cast<float4*>(out + 2 * NE) + e;
    *ao = make_float4(f1, f2, f3, f4);
}

extern "C" void kernel_launch(void* const* d_in, const int* in_sizes, int n_in,
                              void* d_out, int out_size) {
    const float* loc = (const float*)d_in[1];
    float* out = (float*)d_out;

    pack_kernel<<<(N_NODES + 255) / 256, 256>>>(loc);
    knn_kernel<<<N_NODES / WPB, 32 * WPB>>>(out);
}

// round 3
// speedup vs baseline: 3.5100x; 2.1148x over previous
#include <cuda_runtime.h>
#include <cstdint>

#define N_NODES 8192
#define KNN     32
#define NE      (N_NODES * KNN)
#define WPB     4
#define FULL    0xffffffffu

#define G       16
#define NBINS   (G * G)
#define X0      0.1f
#define SINV    (G / 0.9f)     // bins per coordinate unit
#define SW      (0.9f / G)     // bin width

// Scratch (__device__ globals; no allocation allowed)
__device__ float4 g_packed[N_NODES];   // original order: {cx, cy, sq, 0}
__device__ float4 g_attr[N_NODES];     // {w, h, cx, cy}
__device__ float4 g_sorted[N_NODES];   // bin order: {cx, cy, sq, bits(idx)}
__device__ int    g_binCount[NBINS];
__device__ int    g_binStart[NBINS + 1];
__device__ int    g_binCursor[NBINS];

__device__ __forceinline__ int bin_of(float c) {
    int b = (int)((c - X0) * SINV);
    return min(max(b, 0), G - 1);
}

__global__ void zero_kernel() {
    int t = threadIdx.x;
    if (t < NBINS) g_binCount[t] = 0;
}

__global__ void pack_kernel(const float* __restrict__ loc) {
    int i = blockIdx.x * blockDim.x + threadIdx.x;
    if (i >= N_NODES) return;
    const float* r = loc + i * 10;
    float w  = r[4];
    float h  = r[5];
    float cx = r[6];
    float cy = r[7];
    // sq matches jnp.sum(pos*pos): rn(cx*cx)+rn(cy*cy), no fma
    float sq = __fadd_rn(__fmul_rn(cx, cx), __fmul_rn(cy, cy));
    g_packed[i] = make_float4(cx, cy, sq, 0.0f);
    g_attr[i]   = make_float4(w, h, cx, cy);
    atomicAdd(&g_binCount[bin_of(cy) * G + bin_of(cx)], 1);
}

__global__ void prefix_kernel() {
    __shared__ int s[NBINS];
    int t = threadIdx.x;
    int v = g_binCount[t];
    s[t] = v;
    __syncthreads();
    #pragma unroll
    for (int off = 1; off < NBINS; off <<= 1) {
        int add = (t >= off) ? s[t - off] : 0;
        __syncthreads();
        s[t] += add;
        __syncthreads();
    }
    int incl = s[t];
    g_binStart[t]  = incl - v;
    g_binCursor[t] = incl - v;
    if (t == NBINS - 1) g_binStart[NBINS] = incl;
}

__global__ void scatter_kernel() {
    int i = blockIdx.x * blockDim.x + threadIdx.x;
    if (i >= N_NODES) return;
    float4 p = g_packed[i];
    int bin = bin_of(p.y) * G + bin_of(p.x);
    int pos = atomicAdd(&g_binCursor[bin], 1);
    g_sorted[pos] = make_float4(p.x, p.y, p.z, __uint_as_float((unsigned)i));
}

// monotonic float<->uint order mapping
__device__ __forceinline__ unsigned fkey(float f) {
    unsigned u = __float_as_uint(f);
    return (u & 0x80000000u) ? ~u : (u | 0x80000000u);
}
__device__ __forceinline__ float unfkey(unsigned k) {
    unsigned u = (k & 0x80000000u) ? (k ^ 0x80000000u) : ~k;
    return __uint_as_float(u);
}

__global__ void __launch_bounds__(32 * WPB)
knn_kernel(float* __restrict__ out) {
    const int lane = threadIdx.x & 31;
    const int q    = blockIdx.x * WPB + (threadIdx.x >> 5);

    const float4 pq  = g_packed[q];
    const float  qx  = pq.x, qy = pq.y, sqi = pq.z;
    const float  m2x = -2.0f * qx, m2y = -2.0f * qy;  // exact (×2)
    const float  INF = __int_as_float(0x7f800000);
    const int bx = bin_of(qx);
    const int by = bin_of(qy);

    // exact reference-rounded key: (fkey(d2) << 32) | idx
    auto exact_key = [&](float px, float py, float pz, unsigned j) -> unsigned long long {
        float dot = __fmaf_rn(py, qy, __fmul_rn(px, qx));
        float d2  = __fsub_rn(__fadd_rn(sqi, pz), __fmul_rn(2.0f, dot));
        if (j == (unsigned)q) d2 = INF;  // no self loops
        return ((unsigned long long)fkey(d2) << 32) | j;
    };

    unsigned long long slot;
    float thresh, curMax;

    // ---- init: first (up to) 32 candidates of home bin, bitonic sort ----
    const int home = by * G + bx;
    const int hs = g_binStart[home], he = g_binStart[home + 1];
    {
        int i = hs + lane;
        if (i < he) {
            float4 p = g_sorted[i];
            slot = exact_key(p.x, p.y, p.z, __float_as_uint(p.w));
        } else {
            slot = 0xff800000ffffffffULL;  // d2=+inf pad
        }
    }
    #pragma unroll
    for (int k2 = 2; k2 <= 32; k2 <<= 1) {
        #pragma unroll
        for (int j = k2 >> 1; j > 0; j >>= 1) {
            unsigned long long o = __shfl_xor_sync(FULL, slot, j);
            bool keepmin = (((lane & k2) == 0) == ((lane & j) == 0));
            bool take    = keepmin ? (o < slot) : (o > slot);
            if (take) slot = o;
        }
    }

    auto update_thresh = [&]() {
        unsigned hi = (unsigned)(__shfl_sync(FULL, slot, 31) >> 32);
        curMax = unfkey(hi);
        thresh = curMax - sqi + 2e-5f;   // conservative surrogate slack
    };
    update_thresh();

    auto scan_range = [&](int lo, int hiend) {
        for (int base = lo; base < hiend; base += 32) {
            int i = base + lane;
            float4 p;
            float score = INF;
            if (i < hiend) {
                p = g_sorted[i];
                score = __fmaf_rn(p.y, m2y, __fmaf_rn(p.x, m2x, p.z));
            }
            unsigned mask = __ballot_sync(FULL, score < thresh);
            if (!mask) continue;
            do {
                int srcl = __ffs(mask) - 1;
                mask &= mask - 1;
                float px = __shfl_sync(FULL, p.x, srcl);
                float py = __shfl_sync(FULL, p.y, srcl);
                float pz = __shfl_sync(FULL, p.z, srcl);
                unsigned jj = __shfl_sync(FULL, __float_as_uint(p.w), srcl);
                unsigned long long kk = exact_key(px, py, pz, jj);
                // sorted shift-insert; self-rejecting when kk >= slot[31]
                bool gt = (slot > kk);
                unsigned mm = __ballot_sync(FULL, gt);
                unsigned long long o = __shfl_up_sync(FULL, slot, 1);
                if (gt) slot = (lane == __ffs(mm) - 1) ? kk : o;
            } while (mask);
            update_thresh();
        }
    };

    // rest of home bin
    scan_range(hs + 32, he);

    // Chebyshev rings with exact stop bound
    for (int m = 1; m <= 2 * G; m++) {
        // stop check against unscanned region outside block cheb<=(m-1)
        {
            int mm1 = m - 1;
            float dl = (bx - mm1 > 0)     ? (qx - (X0 + (bx - mm1) * SW))       : INF;
            float dr = (bx + mm1 < G - 1) ? ((X0 + (bx + mm1 + 1) * SW) - qx)   : INF;
            float db = (by - mm1 > 0)     ? (qy - (X0 + (by - mm1) * SW))       : INF;
            float dt = (by + mm1 < G - 1) ? ((X0 + (by + mm1 + 1) * SW) - qy)   : INF;
            float dmin = fminf(fminf(dl, dr), fminf(db, dt));
            if (dmin * dmin > curMax + 2e-5f) break;
        }
        int bxlo = max(bx - m, 0), bxhi = min(bx + m, G - 1);
        if (by - m >= 0) {
            int r = (by - m) * G;
            scan_range(g_binStart[r + bxlo], g_binStart[r + bxhi + 1]);
        }
        if (by + m <= G - 1) {
            int r = (by + m) * G;
            scan_range(g_binStart[r + bxlo], g_binStart[r + bxhi + 1]);
        }
        int ylo = max(by - m + 1, 0), yhi = min(by + m - 1, G - 1);
        if (bx - m >= 0) {
            for (int y = ylo; y <= yhi; y++) {
                int b = y * G + bx - m;
                scan_range(g_binStart[b], g_binStart[b + 1]);
            }
        }
        if (bx + m <= G - 1) {
            for (int y = ylo; y <= yhi; y++) {
                int b = y * G + bx + m;
                scan_range(g_binStart[b], g_binStart[b + 1]);
            }
        }
    }

    // ---- outputs (slots ascending = exact top_k order) ----
    const int e = q * KNN + lane;
    const int s = (int)(unsigned)(slot & 0xffffffffu);

    out[e]      = (float)s;  // edge_index[0] (sources)
    out[NE + e] = (float)q;  // edge_index[1] (targets)

    float4 as = g_attr[s];
    float4 at = g_attr[q];
    float hsum = __fadd_rn(as.y, at.y);
    float f1 = __fdiv_rn(__fmul_rn(2.0f, __fsub_rn(as.z, at.z)), hsum);
    float f2 = __fdiv_rn(__fmul_rn(2.0f, __fsub_rn(as.w, at.w)), hsum);
    float f3 = logf(__fdiv_rn(as.x, at.x));
    float f4 = logf(__fdiv_rn(as.y, at.y));

    float4* ao = reinterpret_cast<float4*>(out + 2 * NE) + e;
    *ao = make_float4(f1, f2, f3, f4);
}

extern "C" void kernel_launch(void* const* d_in, const int* in_sizes, int n_in,
                              void* d_out, int out_size) {
    const float* loc = (const float*)d_in[1];
    float* out = (float*)d_out;

    zero_kernel<<<1, 256>>>();
    pack_kernel<<<(N_NODES + 255) / 256, 256>>>(loc);
    prefix_kernel<<<1, NBINS>>>();
    scatter_kernel<<<(N_NODES + 255) / 256, 256>>>();
    knn_kernel<<<N_NODES / WPB, 32 * WPB>>>(out);
}

// round 4
// speedup vs baseline: 3.5745x; 1.0184x over previous
#include <cuda_runtime.h>
#include <cstdint>

#define N_NODES 8192
#define KNN     32
#define NE      (N_NODES * KNN)
#define WPB     8
#define FULL    0xffffffffu

#define G       16
#define NBINS   (G * G)
#define X0      0.1f
#define SINV    (G / 0.9f)     // bins per coordinate unit
#define SW      (0.9f / G)     // bin width

#define PREP_T  1024
#define PPT     (N_NODES / PREP_T)   // 8 points per thread

// Scratch (__device__ globals; no allocation allowed)
__device__ float4 g_attr[N_NODES];     // {w, h, cx, cy} original order
__device__ float4 g_sorted[N_NODES];   // bin order: {cx, cy, sq, bits(idx)}
__device__ int    g_binStart[NBINS + 1];

__device__ __forceinline__ int bin_of(float c) {
    int b = (int)((c - X0) * SINV);
    return min(max(b, 0), G - 1);
}

// One block does everything: pack + histogram + prefix + scatter (smem only)
__global__ void __launch_bounds__(PREP_T)
prep_kernel(const float* __restrict__ loc) {
    __shared__ int hist[NBINS];
    __shared__ int scanb[NBINS];
    __shared__ int cursor[NBINS];
    const int t = threadIdx.x;

    if (t < NBINS) hist[t] = 0;
    __syncthreads();

    float cxr[PPT], cyr[PPT], sqr[PPT];
    int   binr[PPT];
    #pragma unroll
    for (int k = 0; k < PPT; k++) {
        int i = t + k * PREP_T;
        // row byte offset 40*i+16 is 8-aligned -> float2 loads of [w,h],[cx,cy]
        const float2* p2 = reinterpret_cast<const float2*>(loc + i * 10 + 4);
        float2 wh = p2[0];
        float2 cc = p2[1];
        // sq matches jnp.sum(pos*pos): rn(cx*cx)+rn(cy*cy), no fma
        float sq = __fadd_rn(__fmul_rn(cc.x, cc.x), __fmul_rn(cc.y, cc.y));
        g_attr[i] = make_float4(wh.x, wh.y, cc.x, cc.y);
        int b = bin_of(cc.y) * G + bin_of(cc.x);
        atomicAdd(&hist[b], 1);
        cxr[k] = cc.x; cyr[k] = cc.y; sqr[k] = sq; binr[k] = b;
    }
    __syncthreads();

    // Hillis-Steele inclusive scan over 256 bins
    if (t < NBINS) scanb[t] = hist[t];
    __syncthreads();
    #pragma unroll
    for (int off = 1; off < NBINS; off <<= 1) {
        int add = (t < NBINS && t >= off) ? scanb[t - off] : 0;
        __syncthreads();
        if (t < NBINS) scanb[t] += add;
        __syncthreads();
    }
    if (t < NBINS) {
        int excl = scanb[t] - hist[t];
        g_binStart[t] = excl;
        cursor[t] = excl;
        if (t == NBINS - 1) g_binStart[NBINS] = scanb[t];
    }
    __syncthreads();

    #pragma unroll
    for (int k = 0; k < PPT; k++) {
        int i = t + k * PREP_T;
        int pos = atomicAdd(&cursor[binr[k]], 1);
        g_sorted[pos] = make_float4(cxr[k], cyr[k], sqr[k],
                                    __uint_as_float((unsigned)i));
    }
}

// monotonic float<->uint order mapping
__device__ __forceinline__ unsigned fkey(float f) {
    unsigned u = __float_as_uint(f);
    return (u & 0x80000000u) ? ~u : (u | 0x80000000u);
}
__device__ __forceinline__ float unfkey(unsigned k) {
    unsigned u = (k & 0x80000000u) ? (k ^ 0x80000000u) : ~k;
    return __uint_as_float(u);
}

__global__ void __launch_bounds__(32 * WPB)
knn_kernel(float* __restrict__ out) {
    const int lane = threadIdx.x & 31;
    const int p    = blockIdx.x * WPB + (threadIdx.x >> 5);  // sorted position

    // query = point at sorted position p (bin-ordered -> warp locality)
    const float4 sp = g_sorted[p];
    const unsigned q = __float_as_uint(sp.w);
    const float  qx  = sp.x, qy = sp.y, sqi = sp.z;
    const float  m2x = -2.0f * qx, m2y = -2.0f * qy;  // exact (×2)
    const float  INF = __int_as_float(0x7f800000);
    const int bx = bin_of(qx);
    const int by = bin_of(qy);

    // exact reference-rounded key: (fkey(d2) << 32) | idx
    auto exact_key = [&](float px, float py, float pz, unsigned j) -> unsigned long long {
        float dot = __fmaf_rn(py, qy, __fmul_rn(px, qx));
        float d2  = __fsub_rn(__fadd_rn(sqi, pz), __fmul_rn(2.0f, dot));
        if (j == q) d2 = INF;  // no self loops
        return ((unsigned long long)fkey(d2) << 32) | j;
    };

    unsigned long long slot;
    float thresh, curMax;

    // ---- init: first (up to) 32 candidates of home bin, bitonic sort ----
    const int home = by * G + bx;
    const int hs = g_binStart[home], he = g_binStart[home + 1];
    {
        int i = hs + lane;
        if (i < he) {
            float4 pp = g_sorted[i];
            slot = exact_key(pp.x, pp.y, pp.z, __float_as_uint(pp.w));
        } else {
            slot = 0xff800000ffffffffULL;  // d2=+inf pad
        }
    }
    #pragma unroll
    for (int k2 = 2; k2 <= 32; k2 <<= 1) {
        #pragma unroll
        for (int j = k2 >> 1; j > 0; j >>= 1) {
            unsigned long long o = __shfl_xor_sync(FULL, slot, j);
            bool keepmin = (((lane & k2) == 0) == ((lane & j) == 0));
            bool take    = keepmin ? (o < slot) : (o > slot);
            if (take) slot = o;
        }
    }

    auto update_thresh = [&]() {
        unsigned hi = (unsigned)(__shfl_sync(FULL, slot, 31) >> 32);
        curMax = unfkey(hi);
        thresh = curMax - sqi + 2e-5f;   // conservative surrogate slack
    };
    update_thresh();

    auto scan_range = [&](int lo, int hiend) {
        for (int base = lo; base < hiend; base += 32) {
            int i = base + lane;
            float4 pp;
            float score = INF;
            if (i < hiend) {
                pp = g_sorted[i];
                score = __fmaf_rn(pp.y, m2y, __fmaf_rn(pp.x, m2x, pp.z));
            }
            unsigned mask = __ballot_sync(FULL, score < thresh);
            if (!mask) continue;
            do {
                int srcl = __ffs(mask) - 1;
                mask &= mask - 1;
                float px = __shfl_sync(FULL, pp.x, srcl);
                float py = __shfl_sync(FULL, pp.y, srcl);
                float pz = __shfl_sync(FULL, pp.z, srcl);
                unsigned jj = __shfl_sync(FULL, __float_as_uint(pp.w), srcl);
                unsigned long long kk = exact_key(px, py, pz, jj);
                // sorted shift-insert; self-rejecting when kk >= slot[31]
                bool gt = (slot > kk);
                unsigned mm = __ballot_sync(FULL, gt);
                unsigned long long o = __shfl_up_sync(FULL, slot, 1);
                if (gt) slot = (lane == __ffs(mm) - 1) ? kk : o;
            } while (mask);
            update_thresh();
        }
    };

    // rest of home bin
    scan_range(hs + 32, he);

    // Chebyshev rings with exact stop bound
    for (int m = 1; m <= 2 * G; m++) {
        {
            int mm1 = m - 1;
            float dl = (bx - mm1 > 0)     ? (qx - (X0 + (bx - mm1) * SW))     : INF;
            float dr = (bx + mm1 < G - 1) ? ((X0 + (bx + mm1 + 1) * SW) - qx) : INF;
            float db = (by - mm1 > 0)     ? (qy - (X0 + (by - mm1) * SW))     : INF;
            float dt = (by + mm1 < G - 1) ? ((X0 + (by + mm1 + 1) * SW) - qy) : INF;
            float dmin = fminf(fminf(dl, dr), fminf(db, dt));
            if (dmin * dmin > curMax + 2e-5f) break;
        }
        int bxlo = max(bx - m, 0), bxhi = min(bx + m, G - 1);
        if (by - m >= 0) {
            int r = (by - m) * G;
            scan_range(g_binStart[r + bxlo], g_binStart[r + bxhi + 1]);
        }
        if (by + m <= G - 1) {
            int r = (by + m) * G;
            scan_range(g_binStart[r + bxlo], g_binStart[r + bxhi + 1]);
        }
        int ylo = max(by - m + 1, 0), yhi = min(by + m - 1, G - 1);
        if (bx - m >= 0) {
            for (int y = ylo; y <= yhi; y++) {
                int b = y * G + bx - m;
                scan_range(g_binStart[b], g_binStart[b + 1]);
            }
        }
        if (bx + m <= G - 1) {
            for (int y = ylo; y <= yhi; y++) {
                int b = y * G + bx + m;
                scan_range(g_binStart[b], g_binStart[b + 1]);
            }
        }
    }

    // ---- outputs (slots ascending = exact top_k order) ----
    const int e = (int)q * KNN + lane;
    const int s = (int)(unsigned)(slot & 0xffffffffu);

    out[e]      = (float)s;        // edge_index[0] (sources)
    out[NE + e] = (float)q;        // edge_index[1] (targets)

    float4 as = g_attr[s];
    float4 at = g_attr[q];
    float hsum = __fadd_rn(as.y, at.y);
    float f1 = __fdiv_rn(__fmul_rn(2.0f, __fsub_rn(as.z, at.z)), hsum);
    float f2 = __fdiv_rn(__fmul_rn(2.0f, __fsub_rn(as.w, at.w)), hsum);
    float f3 = logf(__fdiv_rn(as.x, at.x));
    float f4 = logf(__fdiv_rn(as.y, at.y));

    float4* ao = reinterpret_cast<float4*>(out + 2 * NE) + e;
    *ao = make_float4(f1, f2, f3, f4);
}

extern "C" void kernel_launch(void* const* d_in, const int* in_sizes, int n_in,
                              void* d_out, int out_size) {
    const float* loc = (const float*)d_in[1];
    float* out = (float*)d_out;

    prep_kernel<<<1, PREP_T>>>(loc);
    knn_kernel<<<N_NODES / WPB, 32 * WPB>>>(out);
}

// round 5
// speedup vs baseline: 4.0029x; 1.1199x over previous
#include <cuda_runtime.h>
#include <cstdint>

#define N_NODES 8192
#define KNN     32
#define NE      (N_NODES * KNN)
#define WPB     8
#define FULL    0xffffffffu

#define G       16
#define NBINS   (G * G)
#define X0      0.1f
#define SINV    (G / 0.9f)     // bins per coordinate unit
#define SW      (0.9f / G)     // bin width

#define PREP_T  1024
#define PPT     (N_NODES / PREP_T)   // 8 points per thread

// Scratch (__device__ globals; no allocation allowed)
__device__ float4 g_attr[N_NODES];     // {w, h, cx, cy} original order
__device__ float4 g_sorted[N_NODES];   // bin order: {cx, cy, sq, bits(idx)}
__device__ int    g_binStart[NBINS + 1];

__device__ __forceinline__ int bin_of(float c) {
    int b = (int)((c - X0) * SINV);
    return min(max(b, 0), G - 1);
}

// One block: pack + smem histogram + warp-shuffle prefix + scatter
__global__ void __launch_bounds__(PREP_T)
prep_kernel(const float* __restrict__ loc) {
    __shared__ int hist[NBINS];
    __shared__ int cursor[NBINS];
    __shared__ int wsum[8];
    const int t = threadIdx.x;

    if (t < NBINS) hist[t] = 0;
    __syncthreads();

    float cxr[PPT], cyr[PPT], sqr[PPT];
    int   binr[PPT];
    #pragma unroll
    for (int k = 0; k < PPT; k++) {
        int i = t + k * PREP_T;
        // row byte offset 40*i+16 is 8-aligned -> float2 loads of [w,h],[cx,cy]
        const float2* p2 = reinterpret_cast<const float2*>(loc + i * 10 + 4);
        float2 wh = p2[0];
        float2 cc = p2[1];
        // sq matches jnp.sum(pos*pos): rn(cx*cx)+rn(cy*cy), no fma
        float sq = __fadd_rn(__fmul_rn(cc.x, cc.x), __fmul_rn(cc.y, cc.y));
        g_attr[i] = make_float4(wh.x, wh.y, cc.x, cc.y);
        int b = bin_of(cc.y) * G + bin_of(cc.x);
        atomicAdd(&hist[b], 1);
        cxr[k] = cc.x; cyr[k] = cc.y; sqr[k] = sq; binr[k] = b;
    }
    __syncthreads();

    // inclusive scan of 256 bins: 8 warp scans + combine
    int v = 0, h = 0;
    if (t < NBINS) {
        h = hist[t];
        v = h;
        #pragma unroll
        for (int off = 1; off < 32; off <<= 1) {
            int n = __shfl_up_sync(FULL, v, off);
            if ((t & 31) >= off) v += n;
        }
        if ((t & 31) == 31) wsum[t >> 5] = v;
    }
    __syncthreads();
    if (t < 8) {
        int s = wsum[t];
        #pragma unroll
        for (int off = 1; off < 8; off <<= 1) {
            int n = __shfl_up_sync(0xffu, s, off);
            if (t >= off) s += n;
        }
        wsum[t] = s;  // inclusive warp-sum prefix
    }
    __syncthreads();
    if (t < NBINS) {
        int incl = v + ((t >= 32) ? wsum[(t >> 5) - 1] : 0);
        int excl = incl - h;
        g_binStart[t] = excl;
        cursor[t] = excl;
        if (t == NBINS - 1) g_binStart[NBINS] = incl;
    }
    __syncthreads();

    #pragma unroll
    for (int k = 0; k < PPT; k++) {
        int i = t + k * PREP_T;
        int pos = atomicAdd(&cursor[binr[k]], 1);
        g_sorted[pos] = make_float4(cxr[k], cyr[k], sqr[k],
                                    __uint_as_float((unsigned)i));
    }
}

// monotonic float<->uint order mapping
__device__ __forceinline__ unsigned fkey(float f) {
    unsigned u = __float_as_uint(f);
    return (u & 0x80000000u) ? ~u : (u | 0x80000000u);
}
__device__ __forceinline__ float unfkey(unsigned k) {
    unsigned u = (k & 0x80000000u) ? (k ^ 0x80000000u) : ~k;
    return __uint_as_float(u);
}

__global__ void __launch_bounds__(32 * WPB, 6)
knn_kernel(float* __restrict__ out) {
    const int lane = threadIdx.x & 31;
    const int p    = blockIdx.x * WPB + (threadIdx.x >> 5);  // sorted position

    // query = point at sorted position p (bin-ordered -> warp locality)
    const float4 sp = g_sorted[p];
    const unsigned q = __float_as_uint(sp.w);
    const float  qx  = sp.x, qy = sp.y, sqi = sp.z;
    const float  m2x = -2.0f * qx, m2y = -2.0f * qy;  // exact (×2)
    const float  INF = __int_as_float(0x7f800000);
    const int bx = bin_of(qx);
    const int by = bin_of(qy);

    // exact reference-rounded key: (fkey(d2) << 32) | idx
    auto exact_key = [&](float px, float py, float pz, unsigned j) -> unsigned long long {
        float dot = __fmaf_rn(py, qy, __fmul_rn(px, qx));
        float d2  = __fsub_rn(__fadd_rn(sqi, pz), __fmul_rn(2.0f, dot));
        if (j == q) d2 = INF;  // no self loops
        return ((unsigned long long)fkey(d2) << 32) | j;
    };

    unsigned long long slot;
    float thresh, curMax;

    // ---- init: first 32 of the middle row segment (3x3 block, row by) ----
    const int bxlo1 = max(bx - 1, 0), bxhi1 = min(bx + 1, G - 1);
    const int ms = g_binStart[by * G + bxlo1];
    const int me = g_binStart[by * G + bxhi1 + 1];
    {
        int i = ms + lane;
        if (i < me) {
            float4 pp = g_sorted[i];
            slot = exact_key(pp.x, pp.y, pp.z, __float_as_uint(pp.w));
        } else {
            slot = 0xff800000ffffffffULL;  // d2=+inf pad
        }
    }
    #pragma unroll
    for (int k2 = 2; k2 <= 32; k2 <<= 1) {
        #pragma unroll
        for (int j = k2 >> 1; j > 0; j >>= 1) {
            unsigned long long o = __shfl_xor_sync(FULL, slot, j);
            bool keepmin = (((lane & k2) == 0) == ((lane & j) == 0));
            bool take    = keepmin ? (o < slot) : (o > slot);
            if (take) slot = o;
        }
    }

    auto update_thresh = [&]() {
        unsigned hi = (unsigned)(__shfl_sync(FULL, slot, 31) >> 32);
        curMax = unfkey(hi);
        thresh = curMax - sqi + 2e-5f;   // conservative surrogate slack
    };
    update_thresh();

    auto scan_range = [&](int lo, int hiend) {
        for (int base = lo; base < hiend; base += 32) {
            int i = base + lane;
            float4 pp;
            float score = INF;
            if (i < hiend) {
                pp = g_sorted[i];
                score = __fmaf_rn(pp.y, m2y, __fmaf_rn(pp.x, m2x, pp.z));
            }
            unsigned mask = __ballot_sync(FULL, score < thresh);
            if (!mask) continue;
            do {
                int srcl = __ffs(mask) - 1;
                mask &= mask - 1;
                float px = __shfl_sync(FULL, pp.x, srcl);
                float py = __shfl_sync(FULL, pp.y, srcl);
                float pz = __shfl_sync(FULL, pp.z, srcl);
                unsigned jj = __shfl_sync(FULL, __float_as_uint(pp.w), srcl);
                unsigned long long kk = exact_key(px, py, pz, jj);
                // sorted shift-insert; self-rejecting when kk >= slot[31]
                bool gt = (slot > kk);
                unsigned mm = __ballot_sync(FULL, gt);
                unsigned long long o = __shfl_up_sync(FULL, slot, 1);
                if (gt) slot = (lane == __ffs(mm) - 1) ? kk : o;
            } while (mask);
            update_thresh();
        }
    };

    // rest of middle row, then rows by-1 / by+1 (full 3-bin contiguous spans)
    scan_range(ms + 32, me);
    if (by - 1 >= 0) {
        int r = (by - 1) * G;
        scan_range(g_binStart[r + bxlo1], g_binStart[r + bxhi1 + 1]);
    }
    if (by + 1 <= G - 1) {
        int r = (by + 1) * G;
        scan_range(g_binStart[r + bxlo1], g_binStart[r + bxhi1 + 1]);
    }

    // Chebyshev rings m>=2 with exact stop bound (cheb<=m-1 fully scanned)
    for (int m = 2; m <= 2 * G; m++) {
        {
            int mm1 = m - 1;
            float dl = (bx - mm1 > 0)     ? (qx - (X0 + (bx - mm1) * SW))     : INF;
            float dr = (bx + mm1 < G - 1) ? ((X0 + (bx + mm1 + 1) * SW) - qx) : INF;
            float db = (by - mm1 > 0)     ? (qy - (X0 + (by - mm1) * SW))     : INF;
            float dt = (by + mm1 < G - 1) ? ((X0 + (by + mm1 + 1) * SW) - qy) : INF;
            float dmin = fminf(fminf(dl, dr), fminf(db, dt));
            if (dmin * dmin > curMax + 2e-5f) break;
        }
        int bxlo = max(bx - m, 0), bxhi = min(bx + m, G - 1);
        if (by - m >= 0) {
            int r = (by - m) * G;
            scan_range(g_binStart[r + bxlo], g_binStart[r + bxhi + 1]);
        }
        if (by + m <= G - 1) {
            int r = (by + m) * G;
            scan_range(g_binStart[r + bxlo], g_binStart[r + bxhi + 1]);
        }
        int ylo = max(by - m + 1, 0), yhi = min(by + m - 1, G - 1);
        if (bx - m >= 0) {
            for (int y = ylo; y <= yhi; y++) {
                int b = y * G + bx - m;
                scan_range(g_binStart[b], g_binStart[b + 1]);
            }
        }
        if (bx + m <= G - 1) {
            for (int y = ylo; y <= yhi; y++) {
                int b = y * G + bx + m;
                scan_range(g_binStart[b], g_binStart[b + 1]);
            }
        }
    }

    // ---- outputs (slots ascending = exact top_k order) ----
    const int e = (int)q * KNN + lane;
    const int s = (int)(unsigned)(slot & 0xffffffffu);

    out[e]      = (float)s;        // edge_index[0] (sources)
    out[NE + e] = (float)q;        // edge_index[1] (targets)

    float4 as = g_attr[s];
    float4 at = g_attr[q];
    float hsum = __fadd_rn(as.y, at.y);
    float f1 = __fdiv_rn(__fmul_rn(2.0f, __fsub_rn(as.z, at.z)), hsum);
    float f2 = __fdiv_rn(__fmul_rn(2.0f, __fsub_rn(as.w, at.w)), hsum);
    float f3 = logf(__fdiv_rn(as.x, at.x));
    float f4 = logf(__fdiv_rn(as.y, at.y));

    float4* ao = reinterpret_cast<float4*>(out + 2 * NE) + e;
    *ao = make_float4(f1, f2, f3, f4);
}

extern "C" void kernel_launch(void* const* d_in, const int* in_sizes, int n_in,
                              void* d_out, int out_size) {
    const float* loc = (const float*)d_in[1];
    float* out = (float*)d_out;

    prep_kernel<<<1, PREP_T>>>(loc);
    knn_kernel<<<N_NODES / WPB, 32 * WPB>>>(out);
}

// round 6
// speedup vs baseline: 4.1781x; 1.0437x over previous
#include <cuda_runtime.h>
#include <cstdint>

#define N_NODES 8192
#define KNN     32
#define NE      (N_NODES * KNN)
#define WPB     8
#define FULL    0xffffffffu

#define G       16
#define NBINS   (G * G)
#define X0      0.1f
#define SINV    (G / 0.9f)     // bins per coordinate unit
#define SW      (0.9f / G)     // bin width

#define NB      4              // prep blocks
#define PREP_T  1024
#define PPT     (N_NODES / (NB * PREP_T))   // 2 points per thread

// Scratch (__device__ globals; no allocation allowed). Zero-initialized at
// module load; barrier counters + hist are reset at end of prep each run.
__device__ float4 g_attr[N_NODES];     // {w, h, cx, cy} original order
__device__ float4 g_sorted[N_NODES];   // bin order: {cx, cy, sq, bits(idx)}
__device__ int    g_binStart[NBINS + 1];
__device__ int    g_hist[NBINS];
__device__ int    g_cursorG[NBINS];
__device__ int    g_bar1, g_bar2, g_bar3;

__device__ __forceinline__ int bin_of(float c) {
    int b = (int)((c - X0) * SINV);
    return min(max(b, 0), G - 1);
}

// Multi-block prep: pack + hist -> spin barrier -> block0 scan -> spin barrier
// -> scatter. Counters/hist reset by the last block for the next graph replay.
__global__ void __launch_bounds__(PREP_T)
prep_kernel(const float* __restrict__ loc) {
    __shared__ int hist[NBINS];
    const int t = threadIdx.x;
    const int b = blockIdx.x;

    if (t < NBINS) hist[t] = 0;
    __syncthreads();

    float cxr[PPT], cyr[PPT], sqr[PPT];
    int   binr[PPT];
    #pragma unroll
    for (int k = 0; k < PPT; k++) {
        int i = b * (PREP_T * PPT) + t + k * PREP_T;
        // row byte offset 40*i+16 is 8-aligned -> float2 loads of [w,h],[cx,cy]
        const float2* p2 = reinterpret_cast<const float2*>(loc + i * 10 + 4);
        float2 wh = p2[0];
        float2 cc = p2[1];
        // sq matches jnp.sum(pos*pos): rn(cx*cx)+rn(cy*cy), no fma
        float sq = __fadd_rn(__fmul_rn(cc.x, cc.x), __fmul_rn(cc.y, cc.y));
        g_attr[i] = make_float4(wh.x, wh.y, cc.x, cc.y);
        int bn = bin_of(cc.y) * G + bin_of(cc.x);
        atomicAdd(&hist[bn], 1);
        cxr[k] = cc.x; cyr[k] = cc.y; sqr[k] = sq; binr[k] = bn;
    }
    __syncthreads();
    if (t < NBINS) atomicAdd(&g_hist[t], hist[t]);
    __threadfence();
    __syncthreads();

    // barrier 1: all blocks' hist contributions visible
    if (t == 0) {
        atomicAdd(&g_bar1, 1);
        while (*((volatile int*)&g_bar1) < NB) {}
        __threadfence();
    }
    __syncthreads();

    // block 0: exclusive scan of 256 bins (warp scans + combine), seed cursors
    if (b == 0) {
        __shared__ int wsum[8];
        int v = 0, h = 0;
        if (t < NBINS) {
            h = g_hist[t];
            v = h;
            #pragma unroll
            for (int off = 1; off < 32; off <<= 1) {
                int n = __shfl_up_sync(FULL, v, off);
                if ((t & 31) >= off) v += n;
            }
            if ((t & 31) == 31) wsum[t >> 5] = v;
        }
        __syncthreads();
        if (t < 8) {
            int s = wsum[t];
            #pragma unroll
            for (int off = 1; off < 8; off <<= 1) {
                int n = __shfl_up_sync(0xffu, s, off);
                if (t >= off) s += n;
            }
            wsum[t] = s;
        }
        __syncthreads();
        if (t < NBINS) {
            int incl = v + ((t >= 32) ? wsum[(t >> 5) - 1] : 0);
            int excl = incl - h;
            g_binStart[t] = excl;
            g_cursorG[t]  = excl;
            if (t == NBINS - 1) g_binStart[NBINS] = incl;
        }
        __threadfence();
        __syncthreads();
        if (t == 0) atomicExch(&g_bar2, 1);
    }

    // barrier 2: cursors ready
    if (t == 0) {
        while (*((volatile int*)&g_bar2) < 1) {}
        __threadfence();
    }
    __syncthreads();

    // scatter via global cursor atomics (bins shared across blocks)
    #pragma unroll
    for (int k = 0; k < PPT; k++) {
        int i = b * (PREP_T * PPT) + t + k * PREP_T;
        int pos = atomicAdd(&g_cursorG[binr[k]], 1);
        g_sorted[pos] = make_float4(cxr[k], cyr[k], sqr[k],
                                    __uint_as_float((unsigned)i));
    }

    // reset shared state for next replay (last block to finish)
    __threadfence();
    __syncthreads();
    if (t == 0) {
        if (atomicAdd(&g_bar3, 1) == NB - 1) {
            for (int i2 = 0; i2 < NBINS; i2++) g_hist[i2] = 0;
            g_bar1 = 0; g_bar2 = 0; g_bar3 = 0;
        }
    }
}

// monotonic float<->uint order mapping
__device__ __forceinline__ unsigned fkey(float f) {
    unsigned u = __float_as_uint(f);
    return (u & 0x80000000u) ? ~u : (u | 0x80000000u);
}
__device__ __forceinline__ float unfkey(unsigned k) {
    unsigned u = (k & 0x80000000u) ? (k ^ 0x80000000u) : ~k;
    return __uint_as_float(u);
}

#define NQW 2                      // queries per warp
#define NW  (N_NODES / NQW)        // total warps (single wave)

__global__ void __launch_bounds__(32 * WPB, 6)
knn_kernel(float* __restrict__ out) {
    const int lane = threadIdx.x & 31;
    const int w    = blockIdx.x * WPB + (threadIdx.x >> 5);
    const float INF = __int_as_float(0x7f800000);

    #pragma unroll 1
    for (int qi = 0; qi < NQW; qi++) {
        const int p = w + qi * NW;            // sorted position (bin-ordered)

        const float4 sp = g_sorted[p];
        const unsigned q = __float_as_uint(sp.w);
        const float  qx  = sp.x, qy = sp.y, sqi = sp.z;
        const float  m2x = -2.0f * qx, m2y = -2.0f * qy;  // exact (×2)
        const int bx = bin_of(qx);
        const int by = bin_of(qy);

        // exact reference-rounded key: (fkey(d2) << 32) | idx
        auto exact_key = [&](float px, float py, float pz, unsigned j) -> unsigned long long {
            float dot = __fmaf_rn(py, qy, __fmul_rn(px, qx));
            float d2  = __fsub_rn(__fadd_rn(sqi, pz), __fmul_rn(2.0f, dot));
            if (j == q) d2 = INF;  // no self loops
            return ((unsigned long long)fkey(d2) << 32) | j;
        };

        unsigned long long slot;
        float thresh, curMax;

        // ---- init: first 32 of middle row segment (3x3 block, row by) ----
        const int bxlo1 = max(bx - 1, 0), bxhi1 = min(bx + 1, G - 1);
        const int ms = g_binStart[by * G + bxlo1];
        const int me = g_binStart[by * G + bxhi1 + 1];
        {
            int i = ms + lane;
            if (i < me) {
                float4 pp = g_sorted[i];
                slot = exact_key(pp.x, pp.y, pp.z, __float_as_uint(pp.w));
            } else {
                slot = 0xffffffffffffffffULL;  // +inf pad
            }
        }
        #pragma unroll
        for (int k2 = 2; k2 <= 32; k2 <<= 1) {
            #pragma unroll
            for (int j = k2 >> 1; j > 0; j >>= 1) {
                unsigned long long o = __shfl_xor_sync(FULL, slot, j);
                bool keepmin = (((lane & k2) == 0) == ((lane & j) == 0));
                bool take    = keepmin ? (o < slot) : (o > slot);
                if (take) slot = o;
            }
        }

        auto update_thresh = [&]() {
            unsigned hi = (unsigned)(__shfl_sync(FULL, slot, 31) >> 32);
            curMax = unfkey(hi);
            thresh = curMax - sqi + 2e-5f;   // conservative surrogate slack
        };
        update_thresh();

        auto scan_range = [&](int lo, int hiend) {
            for (int base = lo; base < hiend; base += 32) {
                int i = base + lane;
                float4 pp = make_float4(0.0f, 0.0f, INF, 0.0f);
                float score = INF;
                if (i < hiend) {
                    pp = g_sorted[i];
                    score = __fmaf_rn(pp.y, m2y, __fmaf_rn(pp.x, m2x, pp.z));
                }
                unsigned mask = __ballot_sync(FULL, score < thresh);
                if (!mask) continue;
                // every lane's exact key, broadcast 64-bit key only
                unsigned long long ck = exact_key(pp.x, pp.y, pp.z,
                                                  __float_as_uint(pp.w));
                do {
                    int srcl = __ffs(mask) - 1;
                    mask &= mask - 1;
                    unsigned long long kk = __shfl_sync(FULL, ck, srcl);
                    // sorted shift-insert; self-rejecting when kk >= slot[31]
                    bool gt = (slot > kk);
                    unsigned mm = __ballot_sync(FULL, gt);
                    unsigned long long o = __shfl_up_sync(FULL, slot, 1);
                    if (gt) slot = (lane == __ffs(mm) - 1) ? kk : o;
                } while (mask);
                update_thresh();
            }
        };

        // rest of middle row, then rows by-1 / by+1 (contiguous 3-bin spans)
        scan_range(ms + 32, me);
        if (by - 1 >= 0) {
            int r = (by - 1) * G;
            scan_range(g_binStart[r + bxlo1], g_binStart[r + bxhi1 + 1]);
        }
        if (by + 1 <= G - 1) {
            int r = (by + 1) * G;
            scan_range(g_binStart[r + bxlo1], g_binStart[r + bxhi1 + 1]);
        }

        // Chebyshev rings m>=2 with exact stop bound
        for (int m = 2; m <= 2 * G; m++) {
            {
                int mm1 = m - 1;
                float dl = (bx - mm1 > 0)     ? (qx - (X0 + (bx - mm1) * SW))     : INF;
                float dr = (bx + mm1 < G - 1) ? ((X0 + (bx + mm1 + 1) * SW) - qx) : INF;
                float db = (by - mm1 > 0)     ? (qy - (X0 + (by - mm1) * SW))     : INF;
                float dt = (by + mm1 < G - 1) ? ((X0 + (by + mm1 + 1) * SW) - qy) : INF;
                float dmin = fminf(fminf(dl, dr), fminf(db, dt));
                if (dmin * dmin > curMax + 2e-5f) break;
            }
            int bxlo = max(bx - m, 0), bxhi = min(bx + m, G - 1);
            if (by - m >= 0) {
                int r = (by - m) * G;
                scan_range(g_binStart[r + bxlo], g_binStart[r + bxhi + 1]);
            }
            if (by + m <= G - 1) {
                int r = (by + m) * G;
                scan_range(g_binStart[r + bxlo], g_binStart[r + bxhi + 1]);
            }
            int ylo = max(by - m + 1, 0), yhi = min(by + m - 1, G - 1);
            if (bx - m >= 0) {
                for (int y = ylo; y <= yhi; y++) {
                    int bb = y * G + bx - m;
                    scan_range(g_binStart[bb], g_binStart[bb + 1]);
                }
            }
            if (bx + m <= G - 1) {
                for (int y = ylo; y <= yhi; y++) {
                    int bb = y * G + bx + m;
                    scan_range(g_binStart[bb], g_binStart[bb + 1]);
                }
            }
        }

        // ---- outputs (slots ascending = exact top_k order) ----
        const int e = (int)q * KNN + lane;
        const int s = (int)(unsigned)(slot & 0xffffffffu);

        out[e]      = (float)s;        // edge_index[0] (sources)
        out[NE + e] = (float)q;        // edge_index[1] (targets)

        float4 as = g_attr[s];
        float4 at = g_attr[q];
        float hsum = __fadd_rn(as.y, at.y);
        float f1 = __fdiv_rn(__fmul_rn(2.0f, __fsub_rn(as.z, at.z)), hsum);
        float f2 = __fdiv_rn(__fmul_rn(2.0f, __fsub_rn(as.w, at.w)), hsum);
        float f3 = logf(__fdiv_rn(as.x, at.x));
        float f4 = logf(__fdiv_rn(as.y, at.y));

        float4* ao = reinterpret_cast<float4*>(out + 2 * NE) + e;
        *ao = make_float4(f1, f2, f3, f4);
    }
}

extern "C" void kernel_launch(void* const* d_in, const int* in_sizes, int n_in,
                              void* d_out, int out_size) {
    const float* loc = (const float*)d_in[1];
    float* out = (float*)d_out;

    prep_kernel<<<NB, PREP_T>>>(loc);
    knn_kernel<<<NW / WPB, 32 * WPB>>>(out);
}

// round 7
// speedup vs baseline: 4.3939x; 1.0517x over previous
#include <cuda_runtime.h>
#include <cstdint>

#define N_NODES 8192
#define KNN     32
#define NE      (N_NODES * KNN)
#define FULL    0xffffffffu

#define G       16
#define NBINS   (G * G)
#define X0      0.1f
#define SINV    (G / 0.9f)     // bins per coordinate unit
#define SW      (0.9f / G)     // bin width

#define NBLK    512
#define TPB     256
#define WPB     (TPB / 32)             // 8 warps/block
#define PPB     (N_NODES / NBLK)       // 16 points per block (prep)
#define NW      (NBLK * WPB)           // 4096 warps
#define NQW     2                      // queries per warp (adjacent)

// Scratch (__device__ globals; zero-initialized at load; barrier/hist state is
// reset at the end of every kernel run for graph replay)
__device__ float4 g_attr[N_NODES];     // {w, h, cx, cy} original order
__device__ float4 g_sorted[N_NODES];   // bin order: {cx, cy, sq, bits(idx)}
__device__ int    g_binStart[NBINS + 1];
__device__ int    g_hist[NBINS];
__device__ int    g_cursorG[NBINS];
__device__ int    g_bar1, g_flagB, g_bar2, g_obs2;

__device__ __forceinline__ int bin_of(float c) {
    int b = (int)((c - X0) * SINV);
    return min(max(b, 0), G - 1);
}

// monotonic float<->uint order mapping
__device__ __forceinline__ unsigned fkey(float f) {
    unsigned u = __float_as_uint(f);
    return (u & 0x80000000u) ? ~u : (u | 0x80000000u);
}
__device__ __forceinline__ float unfkey(unsigned k) {
    unsigned u = (k & 0x80000000u) ? (k ^ 0x80000000u) : ~k;
    return __uint_as_float(u);
}

__global__ void __launch_bounds__(TPB, 6)
fused_kernel(const float* __restrict__ loc, float* __restrict__ out) {
    const int t = threadIdx.x;
    const int b = blockIdx.x;
    const float INF = __int_as_float(0x7f800000);

    // ================= Phase A: pack + global histogram =================
    float cxr = 0.f, cyr = 0.f, sqr = 0.f;
    int   binr = 0, ir = 0;
    if (t < PPB) {
        ir = b * PPB + t;
        // row byte offset 40*i+16 is 8-aligned -> float2 loads of [w,h],[cx,cy]
        const float2* p2 = reinterpret_cast<const float2*>(loc + ir * 10 + 4);
        float2 wh = p2[0];
        float2 cc = p2[1];
        // sq matches jnp.sum(pos*pos): rn(cx*cx)+rn(cy*cy), no fma
        float sq = __fadd_rn(__fmul_rn(cc.x, cc.x), __fmul_rn(cc.y, cc.y));
        g_attr[ir] = make_float4(wh.x, wh.y, cc.x, cc.y);
        binr = bin_of(cc.y) * G + bin_of(cc.x);
        atomicAdd(&g_hist[binr], 1);
        cxr = cc.x; cyr = cc.y; sqr = sq;
    }
    __threadfence();
    __syncthreads();
    if (t == 0) atomicAdd(&g_bar1, 1);

    // ================= Phase B: block 0 scans the 256 bins ===============
    if (b == 0) {
        if (t == 0) {
            while (((volatile int*)&g_bar1)[0] < NBLK) __nanosleep(64);
        }
        __syncthreads();
        __threadfence();
        __shared__ int wsum[8];
        int v = 0, h = 0;
        if (t < NBINS) {
            h = g_hist[t];
            v = h;
            #pragma unroll
            for (int off = 1; off < 32; off <<= 1) {
                int n = __shfl_up_sync(FULL, v, off);
                if ((t & 31) >= off) v += n;
            }
            if ((t & 31) == 31) wsum[t >> 5] = v;
        }
        __syncthreads();
        if (t < 8) {
            int s = wsum[t];
            #pragma unroll
            for (int off = 1; off < 8; off <<= 1) {
                int n = __shfl_up_sync(0xffu, s, off);
                if (t >= off) s += n;
            }
            wsum[t] = s;
        }
        __syncthreads();
        if (t < NBINS) {
            int incl = v + ((t >= 32) ? wsum[(t >> 5) - 1] : 0);
            int excl = incl - h;
            g_binStart[t] = excl;
            g_cursorG[t]  = excl;
            if (t == NBINS - 1) g_binStart[NBINS] = incl;
        }
        __threadfence();
        __syncthreads();
        if (t == 0) atomicExch(&g_flagB, 1);
    }
    if (t == 0) {
        while (((volatile int*)&g_flagB)[0] == 0) __nanosleep(64);
    }
    __syncthreads();
    __threadfence();

    // ================= Phase C: scatter =================================
    if (t < PPB) {
        int pos = atomicAdd(&g_cursorG[binr], 1);
        g_sorted[pos] = make_float4(cxr, cyr, sqr, __uint_as_float((unsigned)ir));
    }
    __threadfence();
    __syncthreads();
    // grid barrier 2 + deadlock-free reset by the LAST observer
    if (t == 0) {
        atomicAdd(&g_bar2, 1);
        while (((volatile int*)&g_bar2)[0] < NBLK) __nanosleep(64);
        int o = atomicAdd(&g_obs2, 1);
        if (o == NBLK - 1) {  // every block has passed both polls: safe to reset
            #pragma unroll 4
            for (int i = 0; i < NBINS; i++) g_hist[i] = 0;
            g_bar1 = 0; g_flagB = 0; g_bar2 = 0; g_obs2 = 0;
            __threadfence();
        }
    }
    __syncthreads();
    __threadfence();

    // ================= Phase D: KNN (2 adjacent queries per warp) ========
    const int lane = threadIdx.x & 31;
    const int w    = b * WPB + (t >> 5);

    #pragma unroll 1
    for (int qi = 0; qi < NQW; qi++) {
        const int p = NQW * w + qi;   // adjacent sorted positions: same bin

        const float4 sp = g_sorted[p];
        const unsigned q = __float_as_uint(sp.w);
        const float  qx  = sp.x, qy = sp.y, sqi = sp.z;
        const float  m2x = -2.0f * qx, m2y = -2.0f * qy;  // exact (×2)
        const int bx = bin_of(qx);
        const int by = bin_of(qy);

        // exact reference-rounded key: (fkey(d2) << 32) | idx
        auto exact_key = [&](float px, float py, float pz, unsigned j) -> unsigned long long {
            float dot = __fmaf_rn(py, qy, __fmul_rn(px, qx));
            float d2  = __fsub_rn(__fadd_rn(sqi, pz), __fmul_rn(2.0f, dot));
            if (j == q) d2 = INF;  // no self loops
            return ((unsigned long long)fkey(d2) << 32) | j;
        };

        unsigned long long slot;
        float thresh, curMax;

        // ---- init: first 32 of middle row segment (3x3 block, row by) ----
        const int bxlo1 = max(bx - 1, 0), bxhi1 = min(bx + 1, G - 1);
        const int ms = g_binStart[by * G + bxlo1];
        const int me = g_binStart[by * G + bxhi1 + 1];
        {
            int i = ms + lane;
            if (i < me) {
                float4 pp = g_sorted[i];
                slot = exact_key(pp.x, pp.y, pp.z, __float_as_uint(pp.w));
            } else {
                slot = 0xffffffffffffffffULL;  // +inf pad
            }
        }
        #pragma unroll
        for (int k2 = 2; k2 <= 32; k2 <<= 1) {
            #pragma unroll
            for (int j = k2 >> 1; j > 0; j >>= 1) {
                unsigned long long o = __shfl_xor_sync(FULL, slot, j);
                bool keepmin = (((lane & k2) == 0) == ((lane & j) == 0));
                bool take    = keepmin ? (o < slot) : (o > slot);
                if (take) slot = o;
            }
        }

        auto update_thresh = [&]() {
            unsigned hi = (unsigned)(__shfl_sync(FULL, slot, 31) >> 32);
            curMax = unfkey(hi);
            thresh = curMax - sqi + 2e-5f;   // conservative surrogate slack
        };
        update_thresh();

        auto scan_range = [&](int lo, int hiend) {
            for (int base = lo; base < hiend; base += 32) {
                int i = base + lane;
                float4 pp = make_float4(0.0f, 0.0f, INF, 0.0f);
                float score = INF;
                if (i < hiend) {
                    pp = g_sorted[i];
                    score = __fmaf_rn(pp.y, m2y, __fmaf_rn(pp.x, m2x, pp.z));
                }
                unsigned mask = __ballot_sync(FULL, score < thresh);
                if (!mask) continue;
                // every lane's exact key, broadcast 64-bit key only
                unsigned long long ck = exact_key(pp.x, pp.y, pp.z,
                                                  __float_as_uint(pp.w));
                do {
                    int srcl = __ffs(mask) - 1;
                    mask &= mask - 1;
                    unsigned long long kk = __shfl_sync(FULL, ck, srcl);
                    // sorted shift-insert; self-rejecting when kk >= slot[31]
                    bool gt = (slot > kk);
                    unsigned mm = __ballot_sync(FULL, gt);
                    unsigned long long o = __shfl_up_sync(FULL, slot, 1);
                    if (gt) slot = (lane == __ffs(mm) - 1) ? kk : o;
                } while (mask);
                update_thresh();
            }
        };

        // rest of middle row, then rows by-1 / by+1 (contiguous 3-bin spans)
        scan_range(ms + 32, me);
        if (by - 1 >= 0) {
            int r = (by - 1) * G;
            scan_range(g_binStart[r + bxlo1], g_binStart[r + bxhi1 + 1]);
        }
        if (by + 1 <= G - 1) {
            int r = (by + 1) * G;
            scan_range(g_binStart[r + bxlo1], g_binStart[r + bxhi1 + 1]);
        }

        // Chebyshev rings m>=2 with exact stop bound
        for (int m = 2; m <= 2 * G; m++) {
            {
                int mm1 = m - 1;
                float dl = (bx - mm1 > 0)     ? (qx - (X0 + (bx - mm1) * SW))     : INF;
                float dr = (bx + mm1 < G - 1) ? ((X0 + (bx + mm1 + 1) * SW) - qx) : INF;
                float db = (by - mm1 > 0)     ? (qy - (X0 + (by - mm1) * SW))     : INF;
                float dt = (by + mm1 < G - 1) ? ((X0 + (by + mm1 + 1) * SW) - qy) : INF;
                float dmin = fminf(fminf(dl, dr), fminf(db, dt));
                if (dmin * dmin > curMax + 2e-5f) break;
            }
            int bxlo = max(bx - m, 0), bxhi = min(bx + m, G - 1);
            if (by - m >= 0) {
                int r = (by - m) * G;
                scan_range(g_binStart[r + bxlo], g_binStart[r + bxhi + 1]);
            }
            if (by + m <= G - 1) {
                int r = (by + m) * G;
                scan_range(g_binStart[r + bxlo], g_binStart[r + bxhi + 1]);
            }
            int ylo = max(by - m + 1, 0), yhi = min(by + m - 1, G - 1);
            if (bx - m >= 0) {
                for (int y = ylo; y <= yhi; y++) {
                    int bb = y * G + bx - m;
                    scan_range(g_binStart[bb], g_binStart[bb + 1]);
                }
            }
            if (bx + m <= G - 1) {
                for (int y = ylo; y <= yhi; y++) {
                    int bb = y * G + bx + m;
                    scan_range(g_binStart[bb], g_binStart[bb + 1]);
                }
            }
        }

        // ---- outputs (slots ascending = exact top_k order) ----
        const int e = (int)q * KNN + lane;
        const int s = (int)(unsigned)(slot & 0xffffffffu);

        out[e]      = (float)s;        // edge_index[0] (sources)
        out[NE + e] = (float)q;        // edge_index[1] (targets)

        float4 as = g_attr[s];
        float4 at = g_attr[q];
        float hsum = __fadd_rn(as.y, at.y);
        float f1 = __fdiv_rn(__fmul_rn(2.0f, __fsub_rn(as.z, at.z)), hsum);
        float f2 = __fdiv_rn(__fmul_rn(2.0f, __fsub_rn(as.w, at.w)), hsum);
        float f3 = logf(__fdiv_rn(as.x, at.x));
        float f4 = logf(__fdiv_rn(as.y, at.y));

        float4* ao = reinterpret_cast<float4*>(out + 2 * NE) + e;
        *ao = make_float4(f1, f2, f3, f4);
    }
}

extern "C" void kernel_launch(void* const* d_in, const int* in_sizes, int n_in,
                              void* d_out, int out_size) {
    const float* loc = (const float*)d_in[1];
    float* out = (float*)d_out;

    fused_kernel<<<NBLK, TPB>>>(loc, out);
}

// round 9
// speedup vs baseline: 4.6610x; 1.0608x over previous
#include <cuda_runtime.h>
#include <cstdint>

#define N_NODES 8192
#define KNN     32
#define NE      (N_NODES * KNN)
#define FULL    0xffffffffu

#define G       16
#define NBINS   (G * G)
#define X0      0.1f
#define SINV    (G / 0.9f)     // bins per coordinate unit
#define SW      (0.9f / G)     // bin width

#define NBLK    512
#define TPB     256
#define WPB     (TPB / 32)             // 8 warps/block
#define PPB     (N_NODES / NBLK)       // 16 points per block (prep)
#define NQW     2                      // queries per warp (adjacent)

#define PADKEY  0xffffffffffffffffULL
#define PADHI   0xffffffffu

// Scratch (__device__ globals; zero-initialized at load; barrier/hist state
// reset at end of every run for graph replay)
__device__ float4 g_attr[N_NODES];     // {w, h, cx, cy} original order
__device__ float4 g_sorted[N_NODES];   // bin order: {cx, cy, sq, bits(idx)}
__device__ int    g_binStart[NBINS + 1];
__device__ int    g_hist[NBINS];
__device__ int    g_bar1, g_flagB, g_bar2, g_obs2;

__device__ __forceinline__ int bin_of(float c) {
    int b = (int)((c - X0) * SINV);
    return min(max(b, 0), G - 1);
}

// monotonic float<->uint order mapping
__device__ __forceinline__ unsigned fkey(float f) {
    unsigned u = __float_as_uint(f);
    return (u & 0x80000000u) ? ~u : (u | 0x80000000u);
}
__device__ __forceinline__ float unfkey(unsigned k) {
    unsigned u = (k & 0x80000000u) ? (k ^ 0x80000000u) : ~k;
    return __uint_as_float(u);
}

__device__ __forceinline__ unsigned long long umin64(unsigned long long a,
                                                     unsigned long long b) {
    return a < b ? a : b;
}
__device__ __forceinline__ unsigned long long umax64(unsigned long long a,
                                                     unsigned long long b) {
    return a > b ? a : b;
}

__global__ void __launch_bounds__(TPB, 6)
fused_kernel(const float* __restrict__ loc, float* __restrict__ out) {
    const int t = threadIdx.x;
    const int b = blockIdx.x;
    const int lane = t & 31;
    const float INF = __int_as_float(0x7f800000);

    // ================= Phase A: pack + global histogram (rank = old) =====
    float cxr = 0.f, cyr = 0.f, sqr = 0.f;
    int   binr = 0, ir = 0, rank = 0;
    if (t < PPB) {
        ir = b * PPB + t;
        // row byte offset 40*i+16 is 8-aligned -> float2 loads [w,h],[cx,cy]
        const float2* p2 = reinterpret_cast<const float2*>(loc + ir * 10 + 4);
        float2 wh = p2[0];
        float2 cc = p2[1];
        // sq matches jnp.sum(pos*pos): rn(cx*cx)+rn(cy*cy), no fma
        float sq = __fadd_rn(__fmul_rn(cc.x, cc.x), __fmul_rn(cc.y, cc.y));
        g_attr[ir] = make_float4(wh.x, wh.y, cc.x, cc.y);
        binr = bin_of(cc.y) * G + bin_of(cc.x);
        rank = atomicAdd(&g_hist[binr], 1);  // in-bin rank
        cxr = cc.x; cyr = cc.y; sqr = sq;
    }
    __threadfence();
    __syncthreads();
    if (t == 0) atomicAdd(&g_bar1, 1);

    // ================= Phase B: block 0 scans the 256 bins ===============
    if (b == 0) {
        if (t == 0) {
            while (((volatile int*)&g_bar1)[0] < NBLK) __nanosleep(32);
        }
        __syncthreads();
        __threadfence();
        __shared__ int wsum[8];
        int v = 0, h = 0;
        if (t < NBINS) {
            h = g_hist[t];
            v = h;
            #pragma unroll
            for (int off = 1; off < 32; off <<= 1) {
                int n = __shfl_up_sync(FULL, v, off);
                if (lane >= off) v += n;
            }
            if (lane == 31) wsum[t >> 5] = v;
        }
        __syncthreads();
        if (t < 8) {
            int s = wsum[t];
            #pragma unroll
            for (int off = 1; off < 8; off <<= 1) {
                int n = __shfl_up_sync(0xffu, s, off);
                if (t >= off) s += n;
            }
            wsum[t] = s;
        }
        __syncthreads();
        if (t < NBINS) {
            int incl = v + ((t >= 32) ? wsum[(t >> 5) - 1] : 0);
            g_binStart[t] = incl - h;
            if (t == NBINS - 1) g_binStart[NBINS] = incl;
        }
        __threadfence();
        __syncthreads();
        if (t == 0) atomicExch(&g_flagB, 1);
    }
    if (t == 0) {
        while (((volatile int*)&g_flagB)[0] == 0) __nanosleep(32);
    }
    __syncthreads();
    __threadfence();

    // ================= Phase C: scatter at binStart + rank ===============
    if (t < PPB) {
        g_sorted[g_binStart[binr] + rank] =
            make_float4(cxr, cyr, sqr, __uint_as_float((unsigned)ir));
    }
    __threadfence();
    __syncthreads();
    // grid barrier 2 + deadlock-free reset by the LAST observer
    if (t == 0) {
        atomicAdd(&g_bar2, 1);
        while (((volatile int*)&g_bar2)[0] < NBLK) __nanosleep(32);
        int o = atomicAdd(&g_obs2, 1);
        if (o == NBLK - 1) {  // all blocks passed both polls: safe to reset
            #pragma unroll 4
            for (int i = 0; i < NBINS; i++) g_hist[i] = 0;
            g_bar1 = 0; g_flagB = 0; g_bar2 = 0; g_obs2 = 0;
            __threadfence();
        }
    }
    __syncthreads();
    __threadfence();

    // ================= Phase D: KNN (2 adjacent queries per warp) ========
    const int w = b * WPB + (t >> 5);

    #pragma unroll 1
    for (int qi = 0; qi < NQW; qi++) {
        const int p = NQW * w + qi;   // adjacent sorted positions: same bin

        const float4 sp = g_sorted[p];
        const unsigned q = __float_as_uint(sp.w);
        const float  qx  = sp.x, qy = sp.y, sqi = sp.z;
        const float  m2x = -2.0f * qx, m2y = -2.0f * qy;  // exact (×2)
        const int bx = bin_of(qx);
        const int by = bin_of(qy);

        // exact reference-rounded key: (fkey(d2) << 32) | idx
        auto exact_key = [&](float px, float py, float pz, unsigned j) -> unsigned long long {
            float dot = __fmaf_rn(py, qy, __fmul_rn(px, qx));
            float d2  = __fsub_rn(__fadd_rn(sqi, pz), __fmul_rn(2.0f, dot));
            if (j == q) d2 = INF;  // no self loops
            return ((unsigned long long)fkey(d2) << 32) | j;
        };

        unsigned long long slot = PADKEY;  // slots start +inf, stay sorted asc
        float curMax = INF;
        float thresh = INF;

        auto update_thresh = [&]() {
            unsigned hi = (unsigned)(__shfl_sync(FULL, slot, 31) >> 32);
            // PAD sentinel decodes to NaN -> clamp to +INF (threshold stays
            // open until 32 REAL keys are resident)
            curMax = (hi == PADHI) ? INF : unfkey(hi);
            thresh = (hi == PADHI) ? INF : (curMax - sqi + 2e-5f);
        };

        auto scan_range = [&](int lo, int hiend) {
            for (int base = lo; base < hiend; base += 32) {
                int i = base + lane;
                float4 pp = make_float4(0.0f, 0.0f, INF, 0.0f);
                float score = INF;
                unsigned jidx = 0;
                if (i < hiend) {
                    pp = g_sorted[i];
                    jidx = __float_as_uint(pp.w);
                    score = __fmaf_rn(pp.y, m2y, __fmaf_rn(pp.x, m2x, pp.z));
                }
                bool hit = (score < thresh) && (i < hiend);
                unsigned mask = __ballot_sync(FULL, hit);
                if (!mask) continue;
                unsigned long long ck = hit ? exact_key(pp.x, pp.y, pp.z, jidx)
                                            : PADKEY;
                if (__popc(mask) <= 3) {
                    // few hits: serial shift-insert (self-rejecting)
                    do {
                        int srcl = __ffs(mask) - 1;
                        mask &= mask - 1;
                        unsigned long long kk = __shfl_sync(FULL, ck, srcl);
                        bool gt = (slot > kk);
                        unsigned mm = __ballot_sync(FULL, gt);
                        unsigned long long o = __shfl_up_sync(FULL, slot, 1);
                        if (gt) slot = (lane == __ffs(mm) - 1) ? kk : o;
                    } while (mask);
                } else {
                    // many hits: bitonic sort candidates asc (15 stages)
                    #pragma unroll
                    for (int k2 = 2; k2 <= 32; k2 <<= 1) {
                        #pragma unroll
                        for (int j = k2 >> 1; j > 0; j >>= 1) {
                            unsigned long long o = __shfl_xor_sync(FULL, ck, j);
                            bool keepmin = (((lane & k2) == 0) == ((lane & j) == 0));
                            ck = keepmin ? umin64(ck, o) : umax64(ck, o);
                        }
                    }
                    // top-32 merge: min(A, reverse(B)) bitonic; 5-stage clean
                    unsigned long long br = __shfl_sync(FULL, ck, 31 - lane);
                    unsigned long long m  = umin64(slot, br);
                    #pragma unroll
                    for (int j = 16; j > 0; j >>= 1) {
                        unsigned long long o = __shfl_xor_sync(FULL, m, j);
                        m = ((lane & j) == 0) ? umin64(m, o) : umax64(m, o);
                    }
                    slot = m;
                }
                update_thresh();
            }
        };

        // home bin FIRST (tightest early threshold), then rest of 3-bin row
        const int bxlo1 = max(bx - 1, 0), bxhi1 = min(bx + 1, G - 1);
        const int rowb = by * G;
        const int hsb = g_binStart[rowb + bx], heb = g_binStart[rowb + bx + 1];
        scan_range(hsb, heb);
        scan_range(g_binStart[rowb + bxlo1], hsb);
        scan_range(heb, g_binStart[rowb + bxhi1 + 1]);
        if (by - 1 >= 0) {
            int r = (by - 1) * G;
            scan_range(g_binStart[r + bxlo1], g_binStart[r + bxhi1 + 1]);
        }
        if (by + 1 <= G - 1) {
            int r = (by + 1) * G;
            scan_range(g_binStart[r + bxlo1], g_binStart[r + bxhi1 + 1]);
        }

        // Chebyshev rings m>=2 with exact stop bound (curMax=INF never stops)
        for (int m = 2; m <= 2 * G; m++) {
            {
                int mm1 = m - 1;
                float dl = (bx - mm1 > 0)     ? (qx - (X0 + (bx - mm1) * SW))     : INF;
                float dr = (bx + mm1 < G - 1) ? ((X0 + (bx + mm1 + 1) * SW) - qx) : INF;
                float db = (by - mm1 > 0)     ? (qy - (X0 + (by - mm1) * SW))     : INF;
                float dt = (by + mm1 < G - 1) ? ((X0 + (by + mm1 + 1) * SW) - qy) : INF;
                float dmin = fminf(fminf(dl, dr), fminf(db, dt));
                if (dmin * dmin > curMax + 2e-5f) break;
            }
            int bxlo = max(bx - m, 0), bxhi = min(bx + m, G - 1);
            if (by - m >= 0) {
                int r = (by - m) * G;
                scan_range(g_binStart[r + bxlo], g_binStart[r + bxhi + 1]);
            }
            if (by + m <= G - 1) {
                int r = (by + m) * G;
                scan_range(g_binStart[r + bxlo], g_binStart[r + bxhi + 1]);
            }
            int ylo = max(by - m + 1, 0), yhi = min(by + m - 1, G - 1);
            if (bx - m >= 0) {
                for (int y = ylo; y <= yhi; y++) {
                    int bb = y * G + bx - m;
                    scan_range(g_binStart[bb], g_binStart[bb + 1]);
                }
            }
            if (bx + m <= G - 1) {
                for (int y = ylo; y <= yhi; y++) {
                    int bb = y * G + bx + m;
                    scan_range(g_binStart[bb], g_binStart[bb + 1]);
                }
            }
        }

        // ---- outputs (slots ascending = exact top_k order) ----
        const int e = (int)q * KNN + lane;
        const int s = (int)(unsigned)(slot & 0xffffffffu);

        out[e]      = (float)s;        // edge_index[0] (sources)
        out[NE + e] = (float)q;        // edge_index[1] (targets)

        float4 as = g_attr[s];
        float4 at = g_attr[q];
        float hsum = __fadd_rn(as.y, at.y);
        float f1 = __fdiv_rn(__fmul_rn(2.0f, __fsub_rn(as.z, at.z)), hsum);
        float f2 = __fdiv_rn(__fmul_rn(2.0f, __fsub_rn(as.w, at.w)), hsum);
        float f3 = logf(__fdiv_rn(as.x, at.x));
        float f4 = logf(__fdiv_rn(as.y, at.y));

        float4* ao = reinterpret_cast<float4*>(out + 2 * NE) + e;
        *ao = make_float4(f1, f2, f3, f4);
    }
}

extern "C" void kernel_launch(void* const* d_in, const int* in_sizes, int n_in,
                              void* d_out, int out_size) {
    const float* loc = (const float*)d_in[1];
    float* out = (float*)d_out;

    fused_kernel<<<NBLK, TPB>>>(loc, out);
}